// round 1
// baseline (speedup 1.0000x reference)
#include <cuda_runtime.h>
#include <cstddef>

#define FULL_MASK 0xFFFFFFFFu

// Problem constants (fixed by setup_inputs)
// B=128, N=196, C=768, heads=12, e=64, num_frames=16
// tokens M = 128*196 = 25088 ; b = 8 ; S = 16*196 = 3136 ; bh = 96
static const int M_TOK = 25088;

// Scratch (allocation-free: __device__ globals)
__device__ float g_qkv[(size_t)25088 * 2304];   // [tok][3*C]  (q|k|v), q/k ReLU'd
__device__ float g_attn[(size_t)25088 * 768];   // attention output before proj
__device__ float g_kv[96 * 64 * 64];            // [bh][e][d]
__device__ float g_ksum[96 * 64];               // [bh][e]

// ---------------------------------------------------------------------------
// C[m,n] = sum_k A[m,k] * B[n,k]   (+bias[n], ReLU for n < relu_limit)
// Requires: M % 128 == 0, N % 128 == 0, K % 8 == 0.
// 128x128 block tile, BK=8, 256 threads, 8x8 per-thread register tile.
// ---------------------------------------------------------------------------
__global__ __launch_bounds__(256) void gemm_nt(
    const float* __restrict__ A, const float* __restrict__ B, float* __restrict__ C,
    int M, int N, int K, const float* __restrict__ bias, int relu_limit)
{
    __shared__ float As[8][128];
    __shared__ float Bs[8][128];

    const int tid  = threadIdx.x;
    const int bm   = blockIdx.y * 128;
    const int bn   = blockIdx.x * 128;
    const int lrow = tid >> 1;           // 0..127
    const int lcol = (tid & 1) * 4;      // 0 or 4
    const int ty   = tid >> 4;           // 0..15
    const int tx   = tid & 15;           // 0..15

    const float* Aptr = A + (size_t)(bm + lrow) * K + lcol;
    const float* Bptr = B + (size_t)(bn + lrow) * K + lcol;

    float acc[8][8];
#pragma unroll
    for (int i = 0; i < 8; i++)
#pragma unroll
        for (int j = 0; j < 8; j++) acc[i][j] = 0.f;

    for (int k0 = 0; k0 < K; k0 += 8) {
        float4 av = *(const float4*)(Aptr + k0);
        float4 bv = *(const float4*)(Bptr + k0);
        As[lcol + 0][lrow] = av.x;
        As[lcol + 1][lrow] = av.y;
        As[lcol + 2][lrow] = av.z;
        As[lcol + 3][lrow] = av.w;
        Bs[lcol + 0][lrow] = bv.x;
        Bs[lcol + 1][lrow] = bv.y;
        Bs[lcol + 2][lrow] = bv.z;
        Bs[lcol + 3][lrow] = bv.w;
        __syncthreads();

#pragma unroll
        for (int kk = 0; kk < 8; kk++) {
            float a[8], b[8];
#pragma unroll
            for (int i = 0; i < 8; i++) a[i] = As[kk][ty * 8 + i];
#pragma unroll
            for (int j = 0; j < 8; j++) b[j] = Bs[kk][tx * 8 + j];
#pragma unroll
            for (int i = 0; i < 8; i++)
#pragma unroll
                for (int j = 0; j < 8; j++) acc[i][j] += a[i] * b[j];
        }
        __syncthreads();
    }

#pragma unroll
    for (int i = 0; i < 8; i++) {
        const int gm = bm + ty * 8 + i;
        float* crow = C + (size_t)gm * N;
#pragma unroll
        for (int j = 0; j < 8; j++) {
            const int gn = bn + tx * 8 + j;
            float v = acc[i][j];
            if (bias) v += bias[gn];
            if (gn < relu_limit) v = fmaxf(v, 0.f);
            crow[gn] = v;
        }
    }
}

// ---------------------------------------------------------------------------
// KV reduction: for each (b,h):  kv[e][d] = sum_s k[s][e]*v[s][d],
//                                k_sum[e] = sum_s k[s][e]
// Grid: 96 blocks (b*12+h), 256 threads. S tiled by 64 through smem.
// Thread owns a 4e x 4d register tile.
// ---------------------------------------------------------------------------
__global__ __launch_bounds__(256) void kv_kernel()
{
    const int bh = blockIdx.x;
    const int b  = bh / 12;
    const int h  = bh % 12;

    __shared__ float Ks[64][64];
    __shared__ float Vs[64][64];

    const int tid = threadIdx.x;
    const int er  = tid >> 4;    // 0..15  -> e rows er*4 .. er*4+3
    const int dg  = tid & 15;    // 0..15  -> d cols dg*4 .. dg*4+3
    const int sl  = tid >> 2;    // 0..63  loader row
    const int ch  = tid & 3;     // 0..3   loader chunk (16 floats)

    float4 acc0 = {0,0,0,0}, acc1 = {0,0,0,0}, acc2 = {0,0,0,0}, acc3 = {0,0,0,0};
    float4 ksum = {0,0,0,0};

    const size_t base_k = (size_t)(b * 3136) * 2304 + 768  + h * 64;
    const size_t base_v = (size_t)(b * 3136) * 2304 + 1536 + h * 64;

    for (int s0 = 0; s0 < 3136; s0 += 64) {
        const float* kp = g_qkv + base_k + (size_t)(s0 + sl) * 2304 + ch * 16;
        const float* vp = g_qkv + base_v + (size_t)(s0 + sl) * 2304 + ch * 16;
#pragma unroll
        for (int c = 0; c < 4; c++) {
            *(float4*)&Ks[sl][ch * 16 + c * 4] = *(const float4*)(kp + c * 4);
            *(float4*)&Vs[sl][ch * 16 + c * 4] = *(const float4*)(vp + c * 4);
        }
        __syncthreads();

#pragma unroll 8
        for (int s = 0; s < 64; s++) {
            float4 k4 = *(const float4*)&Ks[s][er * 4];
            float4 v4 = *(const float4*)&Vs[s][dg * 4];
            acc0.x += k4.x * v4.x; acc0.y += k4.x * v4.y; acc0.z += k4.x * v4.z; acc0.w += k4.x * v4.w;
            acc1.x += k4.y * v4.x; acc1.y += k4.y * v4.y; acc1.z += k4.y * v4.z; acc1.w += k4.y * v4.w;
            acc2.x += k4.z * v4.x; acc2.y += k4.z * v4.y; acc2.z += k4.z * v4.z; acc2.w += k4.z * v4.w;
            acc3.x += k4.w * v4.x; acc3.y += k4.w * v4.y; acc3.z += k4.w * v4.z; acc3.w += k4.w * v4.w;
            if (dg == 0) {
                ksum.x += k4.x; ksum.y += k4.y; ksum.z += k4.z; ksum.w += k4.w;
            }
        }
        __syncthreads();
    }

    float* kvp = g_kv + (size_t)bh * 4096;
    *(float4*)&kvp[(er * 4 + 0) * 64 + dg * 4] = acc0;
    *(float4*)&kvp[(er * 4 + 1) * 64 + dg * 4] = acc1;
    *(float4*)&kvp[(er * 4 + 2) * 64 + dg * 4] = acc2;
    *(float4*)&kvp[(er * 4 + 3) * 64 + dg * 4] = acc3;
    if (dg == 0) *(float4*)&g_ksum[bh * 64 + er * 4] = ksum;
}

// ---------------------------------------------------------------------------
// Output: per token/head:  z = 1/(q . k_sum + eps);  o[d] = (q @ kv)[d] * z
// Grid: (96 bh, 49 chunks of 64 tokens), 256 threads = 8 warps, warp per token.
// ---------------------------------------------------------------------------
__global__ __launch_bounds__(256) void out_kernel()
{
    const int bh    = blockIdx.x;
    const int chunk = blockIdx.y;
    const int b     = bh / 12;
    const int h     = bh % 12;

    __shared__ float KVs[64 * 64];
    __shared__ float ks[64];

    const int tid = threadIdx.x;
    for (int i = tid; i < 1024; i += 256)
        *(float4*)&KVs[i * 4] = *(const float4*)&g_kv[(size_t)bh * 4096 + i * 4];
    if (tid < 16)
        *(float4*)&ks[tid * 4] = *(const float4*)&g_ksum[bh * 64 + tid * 4];
    __syncthreads();

    const int warp = tid >> 5;
    const int lane = tid & 31;

    for (int tloc = warp; tloc < 64; tloc += 8) {
        const int s = chunk * 64 + tloc;
        const size_t tok = (size_t)(b * 3136 + s);
        const float* qp = g_qkv + tok * 2304 + h * 64;   // q, already ReLU'd

        float2 q2 = *(const float2*)(qp + lane * 2);

        float dot = q2.x * ks[lane * 2] + q2.y * ks[lane * 2 + 1];
#pragma unroll
        for (int off = 16; off; off >>= 1) dot += __shfl_xor_sync(FULL_MASK, dot, off);
        const float z = 1.0f / (dot + 1e-4f);

        float2 acc = {0.f, 0.f};
#pragma unroll
        for (int ee = 0; ee < 32; ee++) {
            float qa = __shfl_sync(FULL_MASK, q2.x, ee);
            float qb = __shfl_sync(FULL_MASK, q2.y, ee);
            float2 ka = *(const float2*)&KVs[(2 * ee) * 64 + lane * 2];
            float2 kb = *(const float2*)&KVs[(2 * ee + 1) * 64 + lane * 2];
            acc.x += qa * ka.x + qb * kb.x;
            acc.y += qa * ka.y + qb * kb.y;
        }
        acc.x *= z;
        acc.y *= z;
        *(float2*)&g_attn[tok * 768 + h * 64 + lane * 2] = acc;
    }
}

// ---------------------------------------------------------------------------
extern "C" void kernel_launch(void* const* d_in, const int* in_sizes, int n_in,
                              void* d_out, int out_size)
{
    const float* x     = (const float*)d_in[0];
    const float* Wqkv  = (const float*)d_in[1];
    const float* Wproj = (const float*)d_in[2];
    const float* bproj = (const float*)d_in[3];
    float* out = (float*)d_out;

    float *qkv_p, *attn_p;
    cudaGetSymbolAddress((void**)&qkv_p,  g_qkv);
    cudaGetSymbolAddress((void**)&attn_p, g_attn);

    // 1) qkv = x @ Wqkv^T  with fused ReLU on q,k (cols < 1536)
    dim3 g1(2304 / 128, M_TOK / 128);
    gemm_nt<<<g1, 256>>>(x, Wqkv, qkv_p, M_TOK, 2304, 768, nullptr, 1536);

    // 2) kv and k_sum per (b,h)
    kv_kernel<<<96, 256>>>();

    // 3) normalized q @ kv
    out_kernel<<<dim3(96, 49), 256>>>();

    // 4) final projection: out = attn @ Wproj^T + bproj
    dim3 g3(768 / 128, M_TOK / 128);
    gemm_nt<<<g3, 256>>>(attn_p, Wproj, out, M_TOK, 768, 768, bproj, 0);
}

// round 4
// speedup vs baseline: 1.1432x; 1.1432x over previous
#include <cuda_runtime.h>
#include <cstdint>
#include <cstddef>

#define FULL_MASK 0xFFFFFFFFu

// Problem constants: B=128, N=196, C=768, h=12, e=64, frames=16
// tokens M = 25088 ; b = 8 ; S = 3136 ; bh = 96
static const int M_TOK = 25088;

// Scratch (allocation-free: __device__ globals)
__device__ float g_qkv[(size_t)25088 * 2304];   // [tok][3*C]  (q|k|v), q/k ReLU'd
__device__ float g_attn[(size_t)25088 * 768];   // attention output before proj
__device__ float g_kv[96 * 64 * 64];            // [bh][e][d]
__device__ float g_ksum[96 * 64];               // [bh][e]

// ---------------------------------------------------------------------------
__device__ __forceinline__ float tf32_rna(float x) {
    float r; asm("cvt.rna.tf32.f32 %0, %1;" : "=f"(r) : "f"(x)); return r;
}

// mma.sync m16n8k8 tf32: d += a * b  (row.col, f32 accum)
__device__ __forceinline__ void mma8(float4& d, const uint32_t a[4], const uint32_t b[2]) {
    asm volatile(
        "mma.sync.aligned.m16n8k8.row.col.f32.tf32.tf32.f32 "
        "{%0,%1,%2,%3}, {%4,%5,%6,%7}, {%8,%9}, {%0,%1,%2,%3};"
        : "+f"(d.x), "+f"(d.y), "+f"(d.z), "+f"(d.w)
        : "r"(a[0]), "r"(a[1]), "r"(a[2]), "r"(a[3]), "r"(b[0]), "r"(b[1]));
}

// ---------------------------------------------------------------------------
// 3xTF32 HMMA GEMM:  C[m,n] = sum_k A[m,k]*B[n,k]  (+bias[n], ReLU n<relu_limit)
// M%128==0, N%128==0, K%8==0. 256 threads, 128x128 CTA tile, BK=8,
// double-buffered STATIC smem (34.3KB total) so no cudaFuncSetAttribute needed.
//
// Smem fragment layout per part:
//   A: 8 m-tiles (16 rows each), tile stride 132 floats;
//      addr = tile*132 + reg*32 + frag_lane,  frag_lane = (m&7)*4 + (k&3),
//      reg = ((m>>3)&1) + 2*((k>>2)&1)
//   B: 16 n-tiles (8 rows each), tile stride 68 floats;
//      addr = tile*68 + reg*32 + frag_lane,   reg = (k>>2)&1
// MMA frag loads are base+lane (conflict-free scalar LDS); loader STS are
// float4 (4 consecutive k of one row, same reg) — conflict-free via padding.
// ---------------------------------------------------------------------------
#define APART 1056                  // 8*132
#define BPART 1088                  // 16*68
#define STAGEF (2*APART + 2*BPART)  // 4288 floats = 17152 B

__global__ __launch_bounds__(256) void gemm_tc(
    const float* __restrict__ A, const float* __restrict__ B, float* __restrict__ C,
    int M, int N, int K, const float* __restrict__ bias, int relu_limit)
{
    __shared__ float smem[2][STAGEF];

    const int tid  = threadIdx.x;
    const int bm   = blockIdx.y * 128;
    const int bn   = blockIdx.x * 128;
    const int lane = tid & 31;
    const int warp = tid >> 5;

    // loader: row = tid&127, k-quad = tid>>7
    const int lrow = tid & 127;
    const int lq   = tid >> 7;                  // 0/1
    const float* Aptr = A + (size_t)(bm + lrow) * K + lq * 4;
    const float* Bptr = B + (size_t)(bn + lrow) * K + lq * 4;

    const int aoff = (lrow >> 4) * 132 + (((lrow >> 3) & 1) + 2 * lq) * 32 + (lrow & 7) * 4;
    const int boff = (lrow >> 3) * 68 + lq * 32 + (lrow & 7) * 4;

    float4 acc[4][4];
#pragma unroll
    for (int i = 0; i < 4; i++)
#pragma unroll
        for (int j = 0; j < 4; j++) acc[i][j] = make_float4(0.f, 0.f, 0.f, 0.f);

    auto sts_chunk = [&](float* st, float4 av, float4 bv) {
        float4 h, l;
        h.x = tf32_rna(av.x); h.y = tf32_rna(av.y); h.z = tf32_rna(av.z); h.w = tf32_rna(av.w);
        l.x = tf32_rna(av.x - h.x); l.y = tf32_rna(av.y - h.y);
        l.z = tf32_rna(av.z - h.z); l.w = tf32_rna(av.w - h.w);
        *(float4*)(st + aoff)         = h;
        *(float4*)(st + APART + aoff) = l;
        h.x = tf32_rna(bv.x); h.y = tf32_rna(bv.y); h.z = tf32_rna(bv.z); h.w = tf32_rna(bv.w);
        l.x = tf32_rna(bv.x - h.x); l.y = tf32_rna(bv.y - h.y);
        l.z = tf32_rna(bv.z - h.z); l.w = tf32_rna(bv.w - h.w);
        *(float4*)(st + 2 * APART + boff)         = h;
        *(float4*)(st + 2 * APART + BPART + boff) = l;
    };

    const int NC = K / 8;
    const int wmT = (warp >> 2) * 4;   // A tile base (of 8)
    const int wnT = (warp & 3) * 4;    // B tile base (of 16)

    float4 aR = *(const float4*)Aptr;
    float4 bR = *(const float4*)Bptr;
    sts_chunk(smem[0], aR, bR);
    __syncthreads();

#pragma unroll 1
    for (int kc = 0; kc < NC; kc++) {
        if (kc + 1 < NC) {
            aR = *(const float4*)(Aptr + (kc + 1) * 8);
            bR = *(const float4*)(Bptr + (kc + 1) * 8);
        }

        const float* st = smem[kc & 1];
        const float* Ah = st;
        const float* Al = st + APART;
        const float* Bh = st + 2 * APART;
        const float* Bl = st + 2 * APART + BPART;

        uint32_t ah[4][4], al[4][4], bh[4][2], bl[4][2];
#pragma unroll
        for (int mt = 0; mt < 4; mt++) {
            const int base = (wmT + mt) * 132 + lane;
#pragma unroll
            for (int r = 0; r < 4; r++) {
                ah[mt][r] = __float_as_uint(Ah[base + r * 32]);
                al[mt][r] = __float_as_uint(Al[base + r * 32]);
            }
        }
#pragma unroll
        for (int nt = 0; nt < 4; nt++) {
            const int base = (wnT + nt) * 68 + lane;
#pragma unroll
            for (int r = 0; r < 2; r++) {
                bh[nt][r] = __float_as_uint(Bh[base + r * 32]);
                bl[nt][r] = __float_as_uint(Bl[base + r * 32]);
            }
        }

#pragma unroll
        for (int mt = 0; mt < 4; mt++)
#pragma unroll
            for (int nt = 0; nt < 4; nt++) mma8(acc[mt][nt], ah[mt], bh[nt]);
#pragma unroll
        for (int mt = 0; mt < 4; mt++)
#pragma unroll
            for (int nt = 0; nt < 4; nt++) mma8(acc[mt][nt], al[mt], bh[nt]);
#pragma unroll
        for (int mt = 0; mt < 4; mt++)
#pragma unroll
            for (int nt = 0; nt < 4; nt++) mma8(acc[mt][nt], ah[mt], bl[nt]);

        if (kc + 1 < NC) sts_chunk(smem[(kc + 1) & 1], aR, bR);
        __syncthreads();
    }

    // epilogue: d0:(r,c) d1:(r,c+1) d2:(r+8,c) d3:(r+8,c+1); r=lane/4, c=2*(lane%4)
    const int rbase = bm + (warp >> 2) * 64 + (lane >> 2);
    const int cbase = bn + (warp & 3) * 32 + (lane & 3) * 2;
#pragma unroll
    for (int mt = 0; mt < 4; mt++) {
#pragma unroll
        for (int nt = 0; nt < 4; nt++) {
            const int r = rbase + mt * 16;
            const int c = cbase + nt * 8;
            float4 d = acc[mt][nt];
            if (bias) {
                float2 bb = *(const float2*)(bias + c);
                d.x += bb.x; d.y += bb.y; d.z += bb.x; d.w += bb.y;
            }
            if (c < relu_limit) {
                d.x = fmaxf(d.x, 0.f); d.y = fmaxf(d.y, 0.f);
                d.z = fmaxf(d.z, 0.f); d.w = fmaxf(d.w, 0.f);
            }
            *(float2*)(C + (size_t)r * N + c)       = make_float2(d.x, d.y);
            *(float2*)(C + (size_t)(r + 8) * N + c) = make_float2(d.z, d.w);
        }
    }
}

// ---------------------------------------------------------------------------
// KV reduction: kv[e][d] = sum_s k[s][e]*v[s][d]; k_sum[e]
// ---------------------------------------------------------------------------
__global__ __launch_bounds__(256) void kv_kernel()
{
    const int bh = blockIdx.x;
    const int b  = bh / 12;
    const int h  = bh % 12;

    __shared__ float Ks[64][64];
    __shared__ float Vs[64][64];

    const int tid = threadIdx.x;
    const int er  = tid >> 4;
    const int dg  = tid & 15;
    const int sl  = tid >> 2;
    const int ch  = tid & 3;

    float4 acc0 = {0,0,0,0}, acc1 = {0,0,0,0}, acc2 = {0,0,0,0}, acc3 = {0,0,0,0};
    float4 ksum = {0,0,0,0};

    const size_t base_k = (size_t)(b * 3136) * 2304 + 768  + h * 64;
    const size_t base_v = (size_t)(b * 3136) * 2304 + 1536 + h * 64;

    for (int s0 = 0; s0 < 3136; s0 += 64) {
        const float* kp = g_qkv + base_k + (size_t)(s0 + sl) * 2304 + ch * 16;
        const float* vp = g_qkv + base_v + (size_t)(s0 + sl) * 2304 + ch * 16;
#pragma unroll
        for (int c = 0; c < 4; c++) {
            *(float4*)&Ks[sl][ch * 16 + c * 4] = *(const float4*)(kp + c * 4);
            *(float4*)&Vs[sl][ch * 16 + c * 4] = *(const float4*)(vp + c * 4);
        }
        __syncthreads();

#pragma unroll 8
        for (int s = 0; s < 64; s++) {
            float4 k4 = *(const float4*)&Ks[s][er * 4];
            float4 v4 = *(const float4*)&Vs[s][dg * 4];
            acc0.x += k4.x * v4.x; acc0.y += k4.x * v4.y; acc0.z += k4.x * v4.z; acc0.w += k4.x * v4.w;
            acc1.x += k4.y * v4.x; acc1.y += k4.y * v4.y; acc1.z += k4.y * v4.z; acc1.w += k4.y * v4.w;
            acc2.x += k4.z * v4.x; acc2.y += k4.z * v4.y; acc2.z += k4.z * v4.z; acc2.w += k4.z * v4.w;
            acc3.x += k4.w * v4.x; acc3.y += k4.w * v4.y; acc3.z += k4.w * v4.z; acc3.w += k4.w * v4.w;
            if (dg == 0) {
                ksum.x += k4.x; ksum.y += k4.y; ksum.z += k4.z; ksum.w += k4.w;
            }
        }
        __syncthreads();
    }

    float* kvp = g_kv + (size_t)bh * 4096;
    *(float4*)&kvp[(er * 4 + 0) * 64 + dg * 4] = acc0;
    *(float4*)&kvp[(er * 4 + 1) * 64 + dg * 4] = acc1;
    *(float4*)&kvp[(er * 4 + 2) * 64 + dg * 4] = acc2;
    *(float4*)&kvp[(er * 4 + 3) * 64 + dg * 4] = acc3;
    if (dg == 0) *(float4*)&g_ksum[bh * 64 + er * 4] = ksum;
}

// ---------------------------------------------------------------------------
// Output kernel: z = 1/(q.k_sum+eps); o = (q@kv)*z
// ---------------------------------------------------------------------------
__global__ __launch_bounds__(256) void out_kernel()
{
    const int bh    = blockIdx.x;
    const int chunk = blockIdx.y;
    const int b     = bh / 12;
    const int h     = bh % 12;

    __shared__ float KVs[64 * 64];
    __shared__ float ks[64];

    const int tid = threadIdx.x;
    for (int i = tid; i < 1024; i += 256)
        *(float4*)&KVs[i * 4] = *(const float4*)&g_kv[(size_t)bh * 4096 + i * 4];
    if (tid < 16)
        *(float4*)&ks[tid * 4] = *(const float4*)&g_ksum[bh * 64 + tid * 4];
    __syncthreads();

    const int warp = tid >> 5;
    const int lane = tid & 31;

    for (int tloc = warp; tloc < 64; tloc += 8) {
        const int s = chunk * 64 + tloc;
        const size_t tok = (size_t)(b * 3136 + s);
        const float* qp = g_qkv + tok * 2304 + h * 64;

        float2 q2 = *(const float2*)(qp + lane * 2);

        float dot = q2.x * ks[lane * 2] + q2.y * ks[lane * 2 + 1];
#pragma unroll
        for (int off = 16; off; off >>= 1) dot += __shfl_xor_sync(FULL_MASK, dot, off);
        const float z = 1.0f / (dot + 1e-4f);

        float2 acc = {0.f, 0.f};
#pragma unroll
        for (int ee = 0; ee < 32; ee++) {
            float qa = __shfl_sync(FULL_MASK, q2.x, ee);
            float qb = __shfl_sync(FULL_MASK, q2.y, ee);
            float2 ka = *(const float2*)&KVs[(2 * ee) * 64 + lane * 2];
            float2 kb = *(const float2*)&KVs[(2 * ee + 1) * 64 + lane * 2];
            acc.x += qa * ka.x + qb * kb.x;
            acc.y += qa * ka.y + qb * kb.y;
        }
        acc.x *= z;
        acc.y *= z;
        *(float2*)&g_attn[tok * 768 + h * 64 + lane * 2] = acc;
    }
}

// ---------------------------------------------------------------------------
extern "C" void kernel_launch(void* const* d_in, const int* in_sizes, int n_in,
                              void* d_out, int out_size)
{
    const float* x     = (const float*)d_in[0];
    const float* Wqkv  = (const float*)d_in[1];
    const float* Wproj = (const float*)d_in[2];
    const float* bproj = (const float*)d_in[3];
    float* out = (float*)d_out;

    float *qkv_p, *attn_p;
    cudaGetSymbolAddress((void**)&qkv_p,  g_qkv);
    cudaGetSymbolAddress((void**)&attn_p, g_attn);

    // 1) qkv = x @ Wqkv^T  (fused ReLU on q,k cols < 1536)
    gemm_tc<<<dim3(2304 / 128, M_TOK / 128), 256>>>(
        x, Wqkv, qkv_p, M_TOK, 2304, 768, nullptr, 1536);

    // 2) kv and k_sum per (b,h)
    kv_kernel<<<96, 256>>>();

    // 3) normalized q @ kv
    out_kernel<<<dim3(96, 49), 256>>>();

    // 4) out = attn @ Wproj^T + bproj
    gemm_tc<<<dim3(768 / 128, M_TOK / 128), 256>>>(
        attn_p, Wproj, out, M_TOK, 768, 768, bproj, 0);
}

// round 5
// speedup vs baseline: 2.5979x; 2.2724x over previous
#include <cuda_runtime.h>
#include <cstdint>
#include <cstddef>

#define FULL_MASK 0xFFFFFFFFu

// Problem constants: B=128, N=196, C=768, h=12, e=64, frames=16
// tokens M = 25088 ; b = 8 ; S = 3136 ; bh = 96
static const int M_TOK = 25088;

// ---------------------------------------------------------------------------
// Scratch (allocation-free: __device__ globals)
// ---------------------------------------------------------------------------
__device__ float g_qkv[(size_t)25088 * 2304];   // [tok][3*C]  (q|k|v), q/k ReLU'd
__device__ float g_attn[(size_t)25088 * 768];   // attention output before proj
__device__ float g_kv[96 * 64 * 64];            // [bh][e][d]
__device__ float g_ksum[96 * 64];               // [bh][e]

// bf16x2-split fragment-ordered tiles.
// A-split: [mb][kt][part(2)][mtile(8)][512B]  -> (M/16)*(K/16)*1024 bytes
// B-split: [nb][kt][part(2)][ntile(16)][256B] -> (N/8)*(K/16)*512 bytes
__device__ uint4 g_a1s[(25088 / 16) * (768 / 16) * 64];   // 77.1 MB (x)
__device__ uint4 g_a2s[(25088 / 16) * (768 / 16) * 64];   // 77.1 MB (attn)
__device__ uint4 g_b1s[(2304 / 8) * (768 / 16) * 32];     // 7.1 MB (Wqkv)
__device__ uint4 g_b2s[(768 / 8) * (768 / 16) * 32];      // 2.4 MB (Wproj)

// ---------------------------------------------------------------------------
// helpers
// ---------------------------------------------------------------------------
__device__ __forceinline__ uint32_t smem_u32(const void* p) {
    uint32_t r;
    asm("{.reg .u64 t; cvta.to.shared.u64 t, %1; cvt.u32.u64 %0, t;}" : "=r"(r) : "l"(p));
    return r;
}

// Split float2 -> hi bf16x2 (return) + residual bf16x2 (lo). lo-half = .x
__device__ __forceinline__ uint32_t split2(float2 v, uint32_t& lo) {
    uint32_t b0;
    asm("cvt.rn.bf16x2.f32 %0, %1, %2;" : "=r"(b0) : "f"(v.y), "f"(v.x));
    float f0 = __uint_as_float(b0 << 16);
    float f1 = __uint_as_float(b0 & 0xFFFF0000u);
    float r0 = v.x - f0, r1 = v.y - f1;
    uint32_t b1;
    asm("cvt.rn.bf16x2.f32 %0, %1, %2;" : "=r"(b1) : "f"(r1), "f"(r0));
    lo = b1;
    return b0;
}

// mma.sync m16n8k16 bf16: d += a*b (row.col, f32 accum)
__device__ __forceinline__ void mma16(float4& d, uint4 a, uint2 b) {
    asm volatile(
        "mma.sync.aligned.m16n8k16.row.col.f32.bf16.bf16.f32 "
        "{%0,%1,%2,%3}, {%4,%5,%6,%7}, {%8,%9}, {%0,%1,%2,%3};"
        : "+f"(d.x), "+f"(d.y), "+f"(d.z), "+f"(d.w)
        : "r"(a.x), "r"(a.y), "r"(a.z), "r"(a.w), "r"(b.x), "r"(b.y));
}

// ---------------------------------------------------------------------------
// split_a: fp32 [M][K] row-major -> A-frag tiles (m16n8k16 A operand layout)
// lane l owns regs: a0=(r,c2|c2+1) a1=(r+8,..) a2=(r,c2+8|9) a3=(r+8,..),
//   r=l>>2, c2=(l&3)*2 ; tile bytes: lane*16, tiles [mb][kt][part][mt].
// grid = M/16 strips, 256 threads; warp w handles ktiles w, w+8, ...
// ---------------------------------------------------------------------------
__global__ __launch_bounds__(256) void split_a(const float* __restrict__ src,
                                               uint4* __restrict__ dst, int K)
{
    const int NKT  = K >> 4;
    const int strip = blockIdx.x;
    const int warp = threadIdx.x >> 5, lane = threadIdx.x & 31;
    const int mb = strip >> 3, mt = strip & 7;
    const int c2 = (lane & 3) * 2;
    const float* row0 = src + (size_t)(strip * 16 + (lane >> 2)) * K;
    const float* row1 = row0 + (size_t)8 * K;
    char* base = (char*)dst;

    for (int kt = warp; kt < NKT; kt += 8) {
        const int kb = kt * 16;
        float2 v00 = *(const float2*)(row0 + kb + c2);
        float2 v10 = *(const float2*)(row1 + kb + c2);
        float2 v01 = *(const float2*)(row0 + kb + c2 + 8);
        float2 v11 = *(const float2*)(row1 + kb + c2 + 8);
        uint32_t l0, l1, l2, l3;
        uint32_t h0 = split2(v00, l0);
        uint32_t h1 = split2(v10, l1);
        uint32_t h2 = split2(v01, l2);
        uint32_t h3 = split2(v11, l3);
        size_t off = ((size_t)(mb * NKT + kt) << 13) + mt * 512 + lane * 16;
        *(uint4*)(base + off)        = make_uint4(h0, h1, h2, h3);
        *(uint4*)(base + off + 4096) = make_uint4(l0, l1, l2, l3);
    }
}

// ---------------------------------------------------------------------------
// split_b: fp32 [N][K] row-major -> B-frag tiles (m16n8k16 B operand layout)
// lane l owns: b0=(k=c2|c2+1, n=l>>2), b1=(k=c2+8|9, n) ; tile bytes lane*8.
// grid = N/8 strips.
// ---------------------------------------------------------------------------
__global__ __launch_bounds__(256) void split_b(const float* __restrict__ src,
                                               uint4* __restrict__ dst, int K)
{
    const int NKT  = K >> 4;
    const int strip = blockIdx.x;
    const int warp = threadIdx.x >> 5, lane = threadIdx.x & 31;
    const int nb = strip >> 4, nt = strip & 15;
    const int c2 = (lane & 3) * 2;
    const float* row = src + (size_t)(strip * 8 + (lane >> 2)) * K;
    char* base = (char*)dst;

    for (int kt = warp; kt < NKT; kt += 8) {
        const int kb = kt * 16;
        float2 v0 = *(const float2*)(row + kb + c2);
        float2 v1 = *(const float2*)(row + kb + c2 + 8);
        uint32_t l0, l1;
        uint32_t h0 = split2(v0, l0);
        uint32_t h1 = split2(v1, l1);
        size_t off = ((size_t)(nb * NKT + kt) << 13) + nt * 256 + lane * 8;
        *(uint2*)(base + off)        = make_uint2(h0, h1);
        *(uint2*)(base + off + 4096) = make_uint2(l0, l1);
    }
}

// ---------------------------------------------------------------------------
// bf16x2-3term HMMA GEMM on pre-split tiles.
//   C[m,n] = sum_k A[m,k]*B[n,k]  (+bias[n], ReLU n<relu_limit)
// 256 threads, 128x128 CTA tile, BK=16, 3-stage cp.async ring (48KB static).
// Stage = A slice 8KB (part0|part1, 8 tiles each) + B slice 8KB (part0|part1).
// ---------------------------------------------------------------------------
__global__ __launch_bounds__(256) void gemm_bf16(
    const uint4* __restrict__ As, const uint4* __restrict__ Bs, float* __restrict__ C,
    int M, int N, int K, const float* __restrict__ bias, int relu_limit)
{
    __shared__ char smem[3 * 16384];

    const int tid  = threadIdx.x;
    const int lane = tid & 31;
    const int warp = tid >> 5;
    const int mb   = blockIdx.y;
    const int nb   = blockIdx.x;
    const int NKT  = K >> 4;
    const uint32_t sb = smem_u32(smem);

    const char* Abase = (const char*)As + ((size_t)mb * NKT << 13);
    const char* Bbase = (const char*)Bs + ((size_t)nb * NKT << 13);

    // cp.async one chunk (16KB) into stage kc%3
    auto issue = [&](int kc) {
        const char* asrc = Abase + ((size_t)kc << 13);
        const char* bsrc = Bbase + ((size_t)kc << 13);
        const uint32_t dst0 = sb + (kc % 3) * 16384;
#pragma unroll
        for (int i = 0; i < 2; i++) {
            const int c = tid + i * 256;
            asm volatile("cp.async.ca.shared.global [%0], [%1], 16;"
                         :: "r"(dst0 + c * 16), "l"(asrc + c * 16));
        }
#pragma unroll
        for (int i = 0; i < 2; i++) {
            const int c = tid + i * 256;
            asm volatile("cp.async.ca.shared.global [%0], [%1], 16;"
                         :: "r"(dst0 + 8192 + c * 16), "l"(bsrc + c * 16));
        }
        asm volatile("cp.async.commit_group;");
    };

    float4 acc[4][4];
#pragma unroll
    for (int i = 0; i < 4; i++)
#pragma unroll
        for (int j = 0; j < 4; j++) acc[i][j] = make_float4(0.f, 0.f, 0.f, 0.f);

    const int wm = (warp >> 2) * 4;   // A m-tile base (of 8)
    const int wn = (warp & 3) * 4;    // B n-tile base (of 16)

    issue(0);
    issue(1);

#pragma unroll 1
    for (int kc = 0; kc < NKT; kc++) {
        if (kc + 1 < NKT) asm volatile("cp.async.wait_group 1;" ::: "memory");
        else              asm volatile("cp.async.wait_group 0;" ::: "memory");
        __syncthreads();
        if (kc + 2 < NKT) issue(kc + 2);

        const char* st = smem + (kc % 3) * 16384;

        uint4 ah[4], al[4];
        uint2 bh[4], bl[4];
#pragma unroll
        for (int mt = 0; mt < 4; mt++) {
            ah[mt] = *(const uint4*)(st + (wm + mt) * 512 + lane * 16);
            al[mt] = *(const uint4*)(st + 4096 + (wm + mt) * 512 + lane * 16);
        }
#pragma unroll
        for (int nt = 0; nt < 4; nt++) {
            bh[nt] = *(const uint2*)(st + 8192 + (wn + nt) * 256 + lane * 8);
            bl[nt] = *(const uint2*)(st + 12288 + (wn + nt) * 256 + lane * 8);
        }

#pragma unroll
        for (int mt = 0; mt < 4; mt++)
#pragma unroll
            for (int nt = 0; nt < 4; nt++) mma16(acc[mt][nt], ah[mt], bh[nt]);
#pragma unroll
        for (int mt = 0; mt < 4; mt++)
#pragma unroll
            for (int nt = 0; nt < 4; nt++) mma16(acc[mt][nt], al[mt], bh[nt]);
#pragma unroll
        for (int mt = 0; mt < 4; mt++)
#pragma unroll
            for (int nt = 0; nt < 4; nt++) mma16(acc[mt][nt], ah[mt], bl[nt]);
    }

    // epilogue: d0:(r,c) d1:(r,c+1) d2:(r+8,c) d3:(r+8,c+1); r=lane/4, c=2*(lane%4)
    const int rbase = mb * 128 + (warp >> 2) * 64 + (lane >> 2);
    const int cbase = nb * 128 + (warp & 3) * 32 + (lane & 3) * 2;
#pragma unroll
    for (int mt = 0; mt < 4; mt++) {
#pragma unroll
        for (int nt = 0; nt < 4; nt++) {
            const int r = rbase + mt * 16;
            const int c = cbase + nt * 8;
            float4 d = acc[mt][nt];
            if (bias) {
                float2 bb = *(const float2*)(bias + c);
                d.x += bb.x; d.y += bb.y; d.z += bb.x; d.w += bb.y;
            }
            if (c < relu_limit) {
                d.x = fmaxf(d.x, 0.f); d.y = fmaxf(d.y, 0.f);
                d.z = fmaxf(d.z, 0.f); d.w = fmaxf(d.w, 0.f);
            }
            *(float2*)(C + (size_t)r * N + c)       = make_float2(d.x, d.y);
            *(float2*)(C + (size_t)(r + 8) * N + c) = make_float2(d.z, d.w);
        }
    }
}

// ---------------------------------------------------------------------------
// KV reduction: kv[e][d] = sum_s k[s][e]*v[s][d]; k_sum[e]
// ---------------------------------------------------------------------------
__global__ __launch_bounds__(256) void kv_kernel()
{
    const int bh = blockIdx.x;
    const int b  = bh / 12;
    const int h  = bh % 12;

    __shared__ float Ks[64][64];
    __shared__ float Vs[64][64];

    const int tid = threadIdx.x;
    const int er  = tid >> 4;
    const int dg  = tid & 15;
    const int sl  = tid >> 2;
    const int ch  = tid & 3;

    float4 acc0 = {0,0,0,0}, acc1 = {0,0,0,0}, acc2 = {0,0,0,0}, acc3 = {0,0,0,0};
    float4 ksum = {0,0,0,0};

    const size_t base_k = (size_t)(b * 3136) * 2304 + 768  + h * 64;
    const size_t base_v = (size_t)(b * 3136) * 2304 + 1536 + h * 64;

    for (int s0 = 0; s0 < 3136; s0 += 64) {
        const float* kp = g_qkv + base_k + (size_t)(s0 + sl) * 2304 + ch * 16;
        const float* vp = g_qkv + base_v + (size_t)(s0 + sl) * 2304 + ch * 16;
#pragma unroll
        for (int c = 0; c < 4; c++) {
            *(float4*)&Ks[sl][ch * 16 + c * 4] = *(const float4*)(kp + c * 4);
            *(float4*)&Vs[sl][ch * 16 + c * 4] = *(const float4*)(vp + c * 4);
        }
        __syncthreads();

#pragma unroll 8
        for (int s = 0; s < 64; s++) {
            float4 k4 = *(const float4*)&Ks[s][er * 4];
            float4 v4 = *(const float4*)&Vs[s][dg * 4];
            acc0.x += k4.x * v4.x; acc0.y += k4.x * v4.y; acc0.z += k4.x * v4.z; acc0.w += k4.x * v4.w;
            acc1.x += k4.y * v4.x; acc1.y += k4.y * v4.y; acc1.z += k4.y * v4.z; acc1.w += k4.y * v4.w;
            acc2.x += k4.z * v4.x; acc2.y += k4.z * v4.y; acc2.z += k4.z * v4.z; acc2.w += k4.z * v4.w;
            acc3.x += k4.w * v4.x; acc3.y += k4.w * v4.y; acc3.z += k4.w * v4.z; acc3.w += k4.w * v4.w;
            if (dg == 0) {
                ksum.x += k4.x; ksum.y += k4.y; ksum.z += k4.z; ksum.w += k4.w;
            }
        }
        __syncthreads();
    }

    float* kvp = g_kv + (size_t)bh * 4096;
    *(float4*)&kvp[(er * 4 + 0) * 64 + dg * 4] = acc0;
    *(float4*)&kvp[(er * 4 + 1) * 64 + dg * 4] = acc1;
    *(float4*)&kvp[(er * 4 + 2) * 64 + dg * 4] = acc2;
    *(float4*)&kvp[(er * 4 + 3) * 64 + dg * 4] = acc3;
    if (dg == 0) *(float4*)&g_ksum[bh * 64 + er * 4] = ksum;
}

// ---------------------------------------------------------------------------
// Output kernel: z = 1/(q.k_sum+eps); o = (q@kv)*z
// ---------------------------------------------------------------------------
__global__ __launch_bounds__(256) void out_kernel()
{
    const int bh    = blockIdx.x;
    const int chunk = blockIdx.y;
    const int b     = bh / 12;
    const int h     = bh % 12;

    __shared__ float KVs[64 * 64];
    __shared__ float ks[64];

    const int tid = threadIdx.x;
    for (int i = tid; i < 1024; i += 256)
        *(float4*)&KVs[i * 4] = *(const float4*)&g_kv[(size_t)bh * 4096 + i * 4];
    if (tid < 16)
        *(float4*)&ks[tid * 4] = *(const float4*)&g_ksum[bh * 64 + tid * 4];
    __syncthreads();

    const int warp = tid >> 5;
    const int lane = tid & 31;

    for (int tloc = warp; tloc < 64; tloc += 8) {
        const int s = chunk * 64 + tloc;
        const size_t tok = (size_t)(b * 3136 + s);
        const float* qp = g_qkv + tok * 2304 + h * 64;

        float2 q2 = *(const float2*)(qp + lane * 2);

        float dot = q2.x * ks[lane * 2] + q2.y * ks[lane * 2 + 1];
#pragma unroll
        for (int off = 16; off; off >>= 1) dot += __shfl_xor_sync(FULL_MASK, dot, off);
        const float z = 1.0f / (dot + 1e-4f);

        float2 acc = {0.f, 0.f};
#pragma unroll
        for (int ee = 0; ee < 32; ee++) {
            float qa = __shfl_sync(FULL_MASK, q2.x, ee);
            float qb = __shfl_sync(FULL_MASK, q2.y, ee);
            float2 ka = *(const float2*)&KVs[(2 * ee) * 64 + lane * 2];
            float2 kb = *(const float2*)&KVs[(2 * ee + 1) * 64 + lane * 2];
            acc.x += qa * ka.x + qb * kb.x;
            acc.y += qa * ka.y + qb * kb.y;
        }
        acc.x *= z;
        acc.y *= z;
        *(float2*)&g_attn[tok * 768 + h * 64 + lane * 2] = acc;
    }
}

// ---------------------------------------------------------------------------
extern "C" void kernel_launch(void* const* d_in, const int* in_sizes, int n_in,
                              void* d_out, int out_size)
{
    const float* x     = (const float*)d_in[0];
    const float* Wqkv  = (const float*)d_in[1];
    const float* Wproj = (const float*)d_in[2];
    const float* bproj = (const float*)d_in[3];
    float* out = (float*)d_out;

    float *qkv_p, *attn_p;
    uint4 *a1s, *a2s, *b1s, *b2s;
    cudaGetSymbolAddress((void**)&qkv_p,  g_qkv);
    cudaGetSymbolAddress((void**)&attn_p, g_attn);
    cudaGetSymbolAddress((void**)&a1s, g_a1s);
    cudaGetSymbolAddress((void**)&a2s, g_a2s);
    cudaGetSymbolAddress((void**)&b1s, g_b1s);
    cudaGetSymbolAddress((void**)&b2s, g_b2s);

    // 0) pre-split weights + input into bf16x2 fragment tiles
    split_b<<<2304 / 8, 256>>>(Wqkv,  b1s, 768);
    split_b<<<768 / 8, 256>>>(Wproj, b2s, 768);
    split_a<<<M_TOK / 16, 256>>>(x, a1s, 768);

    // 1) qkv = x @ Wqkv^T  (fused ReLU on q,k cols < 1536)
    gemm_bf16<<<dim3(2304 / 128, M_TOK / 128), 256>>>(
        a1s, b1s, qkv_p, M_TOK, 2304, 768, nullptr, 1536);

    // 2) kv and k_sum per (b,h)
    kv_kernel<<<96, 256>>>();

    // 3) normalized q @ kv
    out_kernel<<<dim3(96, 49), 256>>>();

    // 4) split attn, then out = attn @ Wproj^T + bproj
    split_a<<<M_TOK / 16, 256>>>(attn_p, a2s, 768);
    gemm_bf16<<<dim3(768 / 128, M_TOK / 128), 256>>>(
        a2s, b2s, out, M_TOK, 768, 768, bproj, 0);
}

// round 6
// speedup vs baseline: 3.6870x; 1.4192x over previous
#include <cuda_runtime.h>
#include <cuda_fp16.h>
#include <cstdint>
#include <cstddef>

#define FULL_MASK 0xFFFFFFFFu

// Problem constants: B=128, N=196, C=768, h=12, e=64, frames=16
// tokens M = 25088 ; b = 8 ; S = 3136 ; bh = 96
static const int M_TOK = 25088;

// ---------------------------------------------------------------------------
// Scratch (allocation-free: __device__ globals)
// ---------------------------------------------------------------------------
__device__ float g_qkv[(size_t)25088 * 2304];   // [tok][3*C]  (q|k|v), q/k ReLU'd
__device__ float g_attn[(size_t)25088 * 768];   // attention output before proj
__device__ float g_kv[96 * 64 * 64];            // [bh][e][d]
__device__ float g_ksum[96 * 64];               // [bh][e]
__device__ float g_kvp[7 * 96 * 64 * 64];       // S-split partials
__device__ float g_ksump[7 * 96 * 64];

// fp16-split fragment-ordered tiles.
// A-split: [mb][kt][part(2)][mtile(8)][512B] -> (M/16)*(K/16)*1KB
// B (hi only): [nb][kt][ntile(16)][256B]     -> (N/8)*(K/16)*512B
__device__ uint4 g_a1s[(25088 / 16) * (768 / 16) * 64];   // 77.1 MB (x)
__device__ uint4 g_a2s[(25088 / 16) * (768 / 16) * 64];   // 77.1 MB (attn)
__device__ uint4 g_b1s[(2304 / 8) * (768 / 16) * 16];     // 3.5 MB (Wqkv)
__device__ uint4 g_b2s[(768 / 8) * (768 / 16) * 16];      // 1.2 MB (Wproj)

// ---------------------------------------------------------------------------
__device__ __forceinline__ uint32_t smem_u32(const void* p) {
    uint32_t r;
    asm("{.reg .u64 t; cvta.to.shared.u64 t, %1; cvt.u32.u64 %0, t;}" : "=r"(r) : "l"(p));
    return r;
}

// Split float2 -> hi f16x2 (return) + residual f16x2 (lo). low half = .x
__device__ __forceinline__ uint32_t split2h(float2 v, uint32_t& lo) {
    __half2 h = __float22half2_rn(v);
    float2 back = __half22float2(h);
    __half2 l = __float22half2_rn(make_float2(v.x - back.x, v.y - back.y));
    lo = *(uint32_t*)&l;
    return *(uint32_t*)&h;
}
__device__ __forceinline__ uint32_t cvt2h(float2 v) {
    __half2 h = __float22half2_rn(v);
    return *(uint32_t*)&h;
}

// mma.sync m16n8k16 fp16: d += a*b (row.col, f32 accum)
__device__ __forceinline__ void mma16(float4& d, uint4 a, uint2 b) {
    asm volatile(
        "mma.sync.aligned.m16n8k16.row.col.f32.f16.f16.f32 "
        "{%0,%1,%2,%3}, {%4,%5,%6,%7}, {%8,%9}, {%0,%1,%2,%3};"
        : "+f"(d.x), "+f"(d.y), "+f"(d.z), "+f"(d.w)
        : "r"(a.x), "r"(a.y), "r"(a.z), "r"(a.w), "r"(b.x), "r"(b.y));
}

// ---------------------------------------------------------------------------
// split_a: fp32 [M][K] -> A-frag tiles (hi+lo fp16), m16n8k16 A layout.
// ---------------------------------------------------------------------------
__global__ __launch_bounds__(256) void split_a(const float* __restrict__ src,
                                               uint4* __restrict__ dst, int K)
{
    const int NKT  = K >> 4;
    const int strip = blockIdx.x;
    const int warp = threadIdx.x >> 5, lane = threadIdx.x & 31;
    const int mb = strip >> 3, mt = strip & 7;
    const int c2 = (lane & 3) * 2;
    const float* row0 = src + (size_t)(strip * 16 + (lane >> 2)) * K;
    const float* row1 = row0 + (size_t)8 * K;
    char* base = (char*)dst;

    for (int kt = warp; kt < NKT; kt += 8) {
        const int kb = kt * 16;
        float2 v00 = *(const float2*)(row0 + kb + c2);
        float2 v10 = *(const float2*)(row1 + kb + c2);
        float2 v01 = *(const float2*)(row0 + kb + c2 + 8);
        float2 v11 = *(const float2*)(row1 + kb + c2 + 8);
        uint32_t l0, l1, l2, l3;
        uint32_t h0 = split2h(v00, l0);
        uint32_t h1 = split2h(v10, l1);
        uint32_t h2 = split2h(v01, l2);
        uint32_t h3 = split2h(v11, l3);
        size_t off = ((size_t)(mb * NKT + kt) << 13) + mt * 512 + lane * 16;
        *(uint4*)(base + off)        = make_uint4(h0, h1, h2, h3);
        *(uint4*)(base + off + 4096) = make_uint4(l0, l1, l2, l3);
    }
}

// ---------------------------------------------------------------------------
// split_b: fp32 [N][K] -> B-frag tiles (hi fp16 only), m16n8k16 B layout.
// ---------------------------------------------------------------------------
__global__ __launch_bounds__(256) void split_b(const float* __restrict__ src,
                                               uint4* __restrict__ dst, int K)
{
    const int NKT  = K >> 4;
    const int strip = blockIdx.x;
    const int warp = threadIdx.x >> 5, lane = threadIdx.x & 31;
    const int nb = strip >> 4, nt = strip & 15;
    const int c2 = (lane & 3) * 2;
    const float* row = src + (size_t)(strip * 8 + (lane >> 2)) * K;
    char* base = (char*)dst;

    for (int kt = warp; kt < NKT; kt += 8) {
        const int kb = kt * 16;
        uint32_t h0 = cvt2h(*(const float2*)(row + kb + c2));
        uint32_t h1 = cvt2h(*(const float2*)(row + kb + c2 + 8));
        size_t off = ((size_t)(nb * NKT + kt) << 12) + nt * 256 + lane * 8;
        *(uint2*)(base + off) = make_uint2(h0, h1);
    }
}

// ---------------------------------------------------------------------------
// fp16 2-term HMMA GEMM on pre-split tiles.
//   C[m,n] = sum_k A[m,k]*B[n,k]  (+bias[n], ReLU n<relu_limit)
// 256 threads, 128x128 CTA tile, BK=16, 4-stage cp.async ring (48KB static).
// Stage = A (hi 4KB | lo 4KB) + B hi 4KB = 12KB.
// ---------------------------------------------------------------------------
__global__ __launch_bounds__(256) void gemm_f16(
    const uint4* __restrict__ As, const uint4* __restrict__ Bs, float* __restrict__ C,
    int M, int N, int K, const float* __restrict__ bias, int relu_limit)
{
    __shared__ char smem[4 * 12288];

    const int tid  = threadIdx.x;
    const int lane = tid & 31;
    const int warp = tid >> 5;
    const int mb   = blockIdx.y;
    const int nb   = blockIdx.x;
    const int NKT  = K >> 4;
    const uint32_t sb = smem_u32(smem);

    const char* Abase = (const char*)As + ((size_t)mb * NKT << 13);
    const char* Bbase = (const char*)Bs + ((size_t)nb * NKT << 12);

    auto issue = [&](int kc) {
        const char* asrc = Abase + ((size_t)kc << 13);
        const char* bsrc = Bbase + ((size_t)kc << 12);
        const uint32_t dst0 = sb + (kc & 3) * 12288;
#pragma unroll
        for (int i = 0; i < 2; i++) {
            const int c = tid + i * 256;
            asm volatile("cp.async.ca.shared.global [%0], [%1], 16;"
                         :: "r"(dst0 + c * 16), "l"(asrc + c * 16));
        }
        asm volatile("cp.async.ca.shared.global [%0], [%1], 16;"
                     :: "r"(dst0 + 8192 + tid * 16), "l"(bsrc + tid * 16));
        asm volatile("cp.async.commit_group;");
    };

    float4 acc[4][4];
#pragma unroll
    for (int i = 0; i < 4; i++)
#pragma unroll
        for (int j = 0; j < 4; j++) acc[i][j] = make_float4(0.f, 0.f, 0.f, 0.f);

    const int wm = (warp >> 2) * 4;   // A m-tile base (of 8)
    const int wn = (warp & 3) * 4;    // B n-tile base (of 16)

    issue(0); issue(1); issue(2);

#pragma unroll 1
    for (int kc = 0; kc < NKT; kc++) {
        const int remain = NKT - 1 - kc;
        if (remain >= 2)      asm volatile("cp.async.wait_group 2;" ::: "memory");
        else if (remain == 1) asm volatile("cp.async.wait_group 1;" ::: "memory");
        else                  asm volatile("cp.async.wait_group 0;" ::: "memory");
        __syncthreads();

        const char* st = smem + (kc & 3) * 12288;

        uint4 ah[4], al[4];
        uint2 bh[4];
#pragma unroll
        for (int mt = 0; mt < 4; mt++) {
            ah[mt] = *(const uint4*)(st + (wm + mt) * 512 + lane * 16);
            al[mt] = *(const uint4*)(st + 4096 + (wm + mt) * 512 + lane * 16);
        }
#pragma unroll
        for (int nt = 0; nt < 4; nt++)
            bh[nt] = *(const uint2*)(st + 8192 + (wn + nt) * 256 + lane * 8);

        if (kc + 3 < NKT) issue(kc + 3);

#pragma unroll
        for (int mt = 0; mt < 4; mt++)
#pragma unroll
            for (int nt = 0; nt < 4; nt++) mma16(acc[mt][nt], ah[mt], bh[nt]);
#pragma unroll
        for (int mt = 0; mt < 4; mt++)
#pragma unroll
            for (int nt = 0; nt < 4; nt++) mma16(acc[mt][nt], al[mt], bh[nt]);
    }

    // epilogue: d0:(r,c) d1:(r,c+1) d2:(r+8,c) d3:(r+8,c+1); r=lane/4, c=2*(lane%4)
    const int rbase = mb * 128 + (warp >> 2) * 64 + (lane >> 2);
    const int cbase = nb * 128 + (warp & 3) * 32 + (lane & 3) * 2;
#pragma unroll
    for (int mt = 0; mt < 4; mt++) {
#pragma unroll
        for (int nt = 0; nt < 4; nt++) {
            const int r = rbase + mt * 16;
            const int c = cbase + nt * 8;
            float4 d = acc[mt][nt];
            if (bias) {
                float2 bb = *(const float2*)(bias + c);
                d.x += bb.x; d.y += bb.y; d.z += bb.x; d.w += bb.y;
            }
            if (c < relu_limit) {
                d.x = fmaxf(d.x, 0.f); d.y = fmaxf(d.y, 0.f);
                d.z = fmaxf(d.z, 0.f); d.w = fmaxf(d.w, 0.f);
            }
            *(float2*)(C + (size_t)r * N + c)       = make_float2(d.x, d.y);
            *(float2*)(C + (size_t)(r + 8) * N + c) = make_float2(d.z, d.w);
        }
    }
}

// ---------------------------------------------------------------------------
// KV partial: grid (96, 7); chunk c covers s in [c*448, c*448+448).
// ---------------------------------------------------------------------------
__global__ __launch_bounds__(256) void kv_part()
{
    const int bh = blockIdx.x;
    const int pc = blockIdx.y;
    const int b  = bh / 12;
    const int h  = bh % 12;

    __shared__ float Ks[64][64];
    __shared__ float Vs[64][64];

    const int tid = threadIdx.x;
    const int er  = tid >> 4;
    const int dg  = tid & 15;
    const int sl  = tid >> 2;
    const int ch  = tid & 3;

    float4 acc0 = {0,0,0,0}, acc1 = {0,0,0,0}, acc2 = {0,0,0,0}, acc3 = {0,0,0,0};
    float4 ksum = {0,0,0,0};

    const size_t base_k = (size_t)(b * 3136) * 2304 + 768  + h * 64;
    const size_t base_v = (size_t)(b * 3136) * 2304 + 1536 + h * 64;
    const int s_lo = pc * 448, s_hi = s_lo + 448;

    for (int s0 = s_lo; s0 < s_hi; s0 += 64) {
        const float* kp = g_qkv + base_k + (size_t)(s0 + sl) * 2304 + ch * 16;
        const float* vp = g_qkv + base_v + (size_t)(s0 + sl) * 2304 + ch * 16;
#pragma unroll
        for (int c = 0; c < 4; c++) {
            *(float4*)&Ks[sl][ch * 16 + c * 4] = *(const float4*)(kp + c * 4);
            *(float4*)&Vs[sl][ch * 16 + c * 4] = *(const float4*)(vp + c * 4);
        }
        __syncthreads();

#pragma unroll 8
        for (int s = 0; s < 64; s++) {
            float4 k4 = *(const float4*)&Ks[s][er * 4];
            float4 v4 = *(const float4*)&Vs[s][dg * 4];
            acc0.x += k4.x * v4.x; acc0.y += k4.x * v4.y; acc0.z += k4.x * v4.z; acc0.w += k4.x * v4.w;
            acc1.x += k4.y * v4.x; acc1.y += k4.y * v4.y; acc1.z += k4.y * v4.z; acc1.w += k4.y * v4.w;
            acc2.x += k4.z * v4.x; acc2.y += k4.z * v4.y; acc2.z += k4.z * v4.z; acc2.w += k4.z * v4.w;
            acc3.x += k4.w * v4.x; acc3.y += k4.w * v4.y; acc3.z += k4.w * v4.z; acc3.w += k4.w * v4.w;
            if (dg == 0) {
                ksum.x += k4.x; ksum.y += k4.y; ksum.z += k4.z; ksum.w += k4.w;
            }
        }
        __syncthreads();
    }

    float* kvp = g_kvp + (size_t)(pc * 96 + bh) * 4096;
    *(float4*)&kvp[(er * 4 + 0) * 64 + dg * 4] = acc0;
    *(float4*)&kvp[(er * 4 + 1) * 64 + dg * 4] = acc1;
    *(float4*)&kvp[(er * 4 + 2) * 64 + dg * 4] = acc2;
    *(float4*)&kvp[(er * 4 + 3) * 64 + dg * 4] = acc3;
    if (dg == 0) *(float4*)&g_ksump[(pc * 96 + bh) * 64 + er * 4] = ksum;
}

// Reduce 7 partials (fixed order -> deterministic)
__global__ __launch_bounds__(256) void kv_reduce()
{
    const int bh = blockIdx.x;
    const int tid = threadIdx.x;
#pragma unroll 1
    for (int i = tid * 4; i < 4096; i += 1024) {
        float4 s = make_float4(0.f, 0.f, 0.f, 0.f);
#pragma unroll
        for (int p = 0; p < 7; p++) {
            float4 v = *(const float4*)&g_kvp[(size_t)(p * 96 + bh) * 4096 + i];
            s.x += v.x; s.y += v.y; s.z += v.z; s.w += v.w;
        }
        *(float4*)&g_kv[(size_t)bh * 4096 + i] = s;
    }
    if (tid < 64) {
        float s = 0.f;
#pragma unroll
        for (int p = 0; p < 7; p++) s += g_ksump[(p * 96 + bh) * 64 + tid];
        g_ksum[bh * 64 + tid] = s;
    }
}

// ---------------------------------------------------------------------------
// Output kernel: z = 1/(q.k_sum+eps); o = (q@kv)*z
// ---------------------------------------------------------------------------
__global__ __launch_bounds__(256) void out_kernel()
{
    const int bh    = blockIdx.x;
    const int chunk = blockIdx.y;
    const int b     = bh / 12;
    const int h     = bh % 12;

    __shared__ float KVs[64 * 64];
    __shared__ float ks[64];

    const int tid = threadIdx.x;
    for (int i = tid; i < 1024; i += 256)
        *(float4*)&KVs[i * 4] = *(const float4*)&g_kv[(size_t)bh * 4096 + i * 4];
    if (tid < 16)
        *(float4*)&ks[tid * 4] = *(const float4*)&g_ksum[bh * 64 + tid * 4];
    __syncthreads();

    const int warp = tid >> 5;
    const int lane = tid & 31;

    for (int tloc = warp; tloc < 64; tloc += 8) {
        const int s = chunk * 64 + tloc;
        const size_t tok = (size_t)(b * 3136 + s);
        const float* qp = g_qkv + tok * 2304 + h * 64;

        float2 q2 = *(const float2*)(qp + lane * 2);

        float dot = q2.x * ks[lane * 2] + q2.y * ks[lane * 2 + 1];
#pragma unroll
        for (int off = 16; off; off >>= 1) dot += __shfl_xor_sync(FULL_MASK, dot, off);
        const float z = 1.0f / (dot + 1e-4f);

        float2 acc = {0.f, 0.f};
#pragma unroll
        for (int ee = 0; ee < 32; ee++) {
            float qa = __shfl_sync(FULL_MASK, q2.x, ee);
            float qb = __shfl_sync(FULL_MASK, q2.y, ee);
            float2 ka = *(const float2*)&KVs[(2 * ee) * 64 + lane * 2];
            float2 kb = *(const float2*)&KVs[(2 * ee + 1) * 64 + lane * 2];
            acc.x += qa * ka.x + qb * kb.x;
            acc.y += qa * ka.y + qb * kb.y;
        }
        acc.x *= z;
        acc.y *= z;
        *(float2*)&g_attn[tok * 768 + h * 64 + lane * 2] = acc;
    }
}

// ---------------------------------------------------------------------------
extern "C" void kernel_launch(void* const* d_in, const int* in_sizes, int n_in,
                              void* d_out, int out_size)
{
    const float* x     = (const float*)d_in[0];
    const float* Wqkv  = (const float*)d_in[1];
    const float* Wproj = (const float*)d_in[2];
    const float* bproj = (const float*)d_in[3];
    float* out = (float*)d_out;

    float *qkv_p, *attn_p;
    uint4 *a1s, *a2s, *b1s, *b2s;
    cudaGetSymbolAddress((void**)&qkv_p,  g_qkv);
    cudaGetSymbolAddress((void**)&attn_p, g_attn);
    cudaGetSymbolAddress((void**)&a1s, g_a1s);
    cudaGetSymbolAddress((void**)&a2s, g_a2s);
    cudaGetSymbolAddress((void**)&b1s, g_b1s);
    cudaGetSymbolAddress((void**)&b2s, g_b2s);

    // 0) pre-split weights + input into fp16 fragment tiles
    split_b<<<2304 / 8, 256>>>(Wqkv,  b1s, 768);
    split_b<<<768 / 8, 256>>>(Wproj, b2s, 768);
    split_a<<<M_TOK / 16, 256>>>(x, a1s, 768);

    // 1) qkv = x @ Wqkv^T  (fused ReLU on q,k cols < 1536)
    gemm_f16<<<dim3(2304 / 128, M_TOK / 128), 256>>>(
        a1s, b1s, qkv_p, M_TOK, 2304, 768, nullptr, 1536);

    // 2) kv and k_sum per (b,h): S-split partials + deterministic reduce
    kv_part<<<dim3(96, 7), 256>>>();
    kv_reduce<<<96, 256>>>();

    // 3) normalized q @ kv
    out_kernel<<<dim3(96, 49), 256>>>();

    // 4) split attn, then out = attn @ Wproj^T + bproj
    split_a<<<M_TOK / 16, 256>>>(attn_p, a2s, 768);
    gemm_f16<<<dim3(768 / 128, M_TOK / 128), 256>>>(
        a2s, b2s, out, M_TOK, 768, 768, bproj, 0);
}